// round 1
// baseline (speedup 1.0000x reference)
#include <cuda_runtime.h>

// Problem constants: inputs are (8, 3, 512, 512) float32; output is 1 float (mean L1).
#define WD 512
#define HT 512
#define NC 24            // N*C planes per image
#define RAD 5
constexpr float EPSV   = 1e-6f;
constexpr float INV_KK = 1.0f / 121.0f;          // 1/(11*11)
constexpr int   EPLANE = WD * HT;                // 262144
constexpr int   EIMG   = NC * EPLANE;            // 6291456
constexpr float SCALE  = 1.0f / 6291456.0f;      // 1/EIMG for the mean
constexpr int   CH     = 64;                     // rows per vertical-pass chunk
constexpr int   VTX    = 128;                    // threads.x for vertical pass

// Static scratch (allocation-free rule): 6 image-sized buffers, ~151 MB total.
__device__ float g_h1 [EIMG];   // horizontal box sums (field 1)
__device__ float g_h2 [EIMG];   // horizontal box sums (field 2)
__device__ float g_a  [EIMG];   // guided-filter 'a'
__device__ float g_b  [EIMG];   // guided-filter 'b'
__device__ float g_irf[EIMG];   // filtered ir
__device__ float g_vif[EIMG];   // filtered vi

// ---------------------------------------------------------------------------
// K1: horizontal 11-tap box sums of x and x^2 (zero padding outside row).
// One block per row (NC*HT rows), WD threads.
// ---------------------------------------------------------------------------
__global__ void hbox_sq(const float* __restrict__ x) {
    const int row  = blockIdx.x;
    const int t    = threadIdx.x;
    const size_t base = (size_t)row * WD;
    __shared__ float s[WD];
    s[t] = x[base + t];
    __syncthreads();
    float s1 = 0.f, s2 = 0.f;
#pragma unroll
    for (int d = -RAD; d <= RAD; ++d) {
        int j = t + d;
        if ((unsigned)j < (unsigned)WD) {
            float u = s[j];
            s1 += u;
            s2 = fmaf(u, u, s2);
        }
    }
    g_h1[base + t] = s1;
    g_h2[base + t] = s2;
}

// ---------------------------------------------------------------------------
// K3: horizontal 11-tap box sums of a and b.
// ---------------------------------------------------------------------------
__global__ void hbox_ab() {
    const int row  = blockIdx.x;
    const int t    = threadIdx.x;
    const size_t base = (size_t)row * WD;
    __shared__ float sa[WD];
    __shared__ float sb[WD];
    sa[t] = g_a[base + t];
    sb[t] = g_b[base + t];
    __syncthreads();
    float s1 = 0.f, s2 = 0.f;
#pragma unroll
    for (int d = -RAD; d <= RAD; ++d) {
        int j = t + d;
        if ((unsigned)j < (unsigned)WD) {
            s1 += sa[j];
            s2 += sb[j];
        }
    }
    g_h1[base + t] = s1;
    g_h2[base + t] = s2;
}

// ---------------------------------------------------------------------------
// K2: vertical sliding box sum over g_h1/g_h2 -> mean, corr -> a, b.
// Each thread walks CH rows of one column. Grid: (WD/VTX, HT/CH, NC).
// ---------------------------------------------------------------------------
__global__ void vbox_ab() {
    const int xcol  = blockIdx.x * VTX + threadIdx.x;
    const int y0    = blockIdx.y * CH;
    const int plane = blockIdx.z;
    const size_t base = (size_t)plane * EPLANE + xcol;

    float s1 = 0.f, s2 = 0.f;
#pragma unroll
    for (int d = -RAD; d <= RAD; ++d) {
        int r = y0 + d;
        if ((unsigned)r < (unsigned)HT) {
            s1 += g_h1[base + (size_t)r * WD];
            s2 += g_h2[base + (size_t)r * WD];
        }
    }
    for (int y = y0; y < y0 + CH; ++y) {
        float mean = s1 * INV_KK;
        float corr = s2 * INV_KK;
        float var  = corr - mean * mean;
        float aa   = var / (var + EPSV);
        float bb   = mean - aa * mean;
        size_t idx = base + (size_t)y * WD;
        g_a[idx] = aa;
        g_b[idx] = bb;
        int yn = y + RAD + 1;
        int yo = y - RAD;
        if (yn < HT) {
            s1 += g_h1[base + (size_t)yn * WD];
            s2 += g_h2[base + (size_t)yn * WD];
        }
        if (yo >= 0) {
            s1 -= g_h1[base + (size_t)yo * WD];
            s2 -= g_h2[base + (size_t)yo * WD];
        }
    }
}

// ---------------------------------------------------------------------------
// K4 (ir/vi): vertical sliding box sum over g_h1/g_h2 (= rowsums of a,b),
// combine with x: f = x - (meanA*x + meanB). which: 0 -> g_irf, 1 -> g_vif.
// ---------------------------------------------------------------------------
__global__ void vbox_final_store(const float* __restrict__ x, int which) {
    const int xcol  = blockIdx.x * VTX + threadIdx.x;
    const int y0    = blockIdx.y * CH;
    const int plane = blockIdx.z;
    const size_t base = (size_t)plane * EPLANE + xcol;
    float* __restrict__ f = (which == 0) ? g_irf : g_vif;

    float s1 = 0.f, s2 = 0.f;
#pragma unroll
    for (int d = -RAD; d <= RAD; ++d) {
        int r = y0 + d;
        if ((unsigned)r < (unsigned)HT) {
            s1 += g_h1[base + (size_t)r * WD];
            s2 += g_h2[base + (size_t)r * WD];
        }
    }
    for (int y = y0; y < y0 + CH; ++y) {
        float ma = s1 * INV_KK;
        float mb = s2 * INV_KK;
        size_t idx = base + (size_t)y * WD;
        float xv = x[idx];
        f[idx] = xv - fmaf(ma, xv, mb);
        int yn = y + RAD + 1;
        int yo = y - RAD;
        if (yn < HT) {
            s1 += g_h1[base + (size_t)yn * WD];
            s2 += g_h2[base + (size_t)yn * WD];
        }
        if (yo >= 0) {
            s1 -= g_h1[base + (size_t)yo * WD];
            s2 -= g_h2[base + (size_t)yo * WD];
        }
    }
}

// ---------------------------------------------------------------------------
// K4 (gen): same vertical combine, fused with the L1-vs-max loss reduction.
// Block partial sums scaled by 1/EIMG, atomicAdd into out[0].
// ---------------------------------------------------------------------------
__global__ void vbox_final_loss(const float* __restrict__ x, float* __restrict__ out) {
    const int xcol  = blockIdx.x * VTX + threadIdx.x;
    const int y0    = blockIdx.y * CH;
    const int plane = blockIdx.z;
    const size_t base = (size_t)plane * EPLANE + xcol;

    float s1 = 0.f, s2 = 0.f;
#pragma unroll
    for (int d = -RAD; d <= RAD; ++d) {
        int r = y0 + d;
        if ((unsigned)r < (unsigned)HT) {
            s1 += g_h1[base + (size_t)r * WD];
            s2 += g_h2[base + (size_t)r * WD];
        }
    }
    float acc = 0.f;
    for (int y = y0; y < y0 + CH; ++y) {
        float ma = s1 * INV_KK;
        float mb = s2 * INV_KK;
        size_t idx = base + (size_t)y * WD;
        float xv = x[idx];
        float fg = xv - fmaf(ma, xv, mb);
        float fl = fmaxf(fabsf(g_irf[idx]), fabsf(g_vif[idx]));
        acc += fabsf(fg - fl);
        int yn = y + RAD + 1;
        int yo = y - RAD;
        if (yn < HT) {
            s1 += g_h1[base + (size_t)yn * WD];
            s2 += g_h2[base + (size_t)yn * WD];
        }
        if (yo >= 0) {
            s1 -= g_h1[base + (size_t)yo * WD];
            s2 -= g_h2[base + (size_t)yo * WD];
        }
    }
    // warp reduce
#pragma unroll
    for (int o = 16; o; o >>= 1) acc += __shfl_down_sync(0xffffffffu, acc, o);
    __shared__ float wsum[VTX / 32];
    int lane = threadIdx.x & 31;
    int wid  = threadIdx.x >> 5;
    if (lane == 0) wsum[wid] = acc;
    __syncthreads();
    if (wid == 0) {
        float v = (lane < (VTX / 32)) ? wsum[lane] : 0.f;
#pragma unroll
        for (int o = 16; o; o >>= 1) v += __shfl_down_sync(0xffffffffu, v, o);
        if (lane == 0) atomicAdd(out, v * SCALE);
    }
}

__global__ void zero_out(float* out) { out[0] = 0.f; }

// ---------------------------------------------------------------------------
extern "C" void kernel_launch(void* const* d_in, const int* in_sizes, int n_in,
                              void* d_out, int out_size) {
    const float* gen = (const float*)d_in[0];
    const float* ir  = (const float*)d_in[1];
    const float* vi  = (const float*)d_in[2];
    float* out = (float*)d_out;

    dim3 hgrid(NC * HT);               // 12288 blocks of WD threads
    dim3 vgrid(WD / VTX, HT / CH, NC); // (4, 8, 24)

    zero_out<<<1, 1>>>(out);

    // ir
    hbox_sq<<<hgrid, WD>>>(ir);
    vbox_ab<<<vgrid, VTX>>>();
    hbox_ab<<<hgrid, WD>>>();
    vbox_final_store<<<vgrid, VTX>>>(ir, 0);

    // vi
    hbox_sq<<<hgrid, WD>>>(vi);
    vbox_ab<<<vgrid, VTX>>>();
    hbox_ab<<<hgrid, WD>>>();
    vbox_final_store<<<vgrid, VTX>>>(vi, 1);

    // gen + fused loss
    hbox_sq<<<hgrid, WD>>>(gen);
    vbox_ab<<<vgrid, VTX>>>();
    hbox_ab<<<hgrid, WD>>>();
    vbox_final_loss<<<vgrid, VTX>>>(gen, out);
}

// round 3
// speedup vs baseline: 2.5804x; 2.5804x over previous
#include <cuda_runtime.h>

// Inputs: (8,3,512,512) fp32 x3 (general, ir, vi). Output: 1 float (mean L1).
#define WD   512
#define HT   512
#define NPL  24          // N*C planes
#define RAD  5
#define CT   128         // output cols per block
#define ABW  138         // CT + 2*RAD  (a,b column range)
#define XW   148         // CT + 4*RAD  (x column range)
#define BANDQ 171        // nominal rows per block (512 = 171+171+170)
#define NTH  160         // 5 warps
#define NWARP (NTH/32)

constexpr float EPSV   = 1e-6f;
constexpr float INV_KK = 1.0f / 121.0f;
constexpr int   EPLANE = WD * HT;
constexpr float SCALE  = 1.0f / (float)(NPL * EPLANE);

// ---- dynamic shared layout (float units) ----------------------------------
constexpr int OFF_ROWX = 0;                       // [2][3][XW]
constexpr int SZ_ROWX  = 2 * 3 * XW;              // 888
constexpr int OFF_XC   = OFF_ROWX + SZ_ROWX;      // [3][12][CT]  (12 slots: race fix)
constexpr int SZ_XC    = 3 * 12 * CT;             // 4608
constexpr int OFF_HC   = OFF_XC + SZ_XC;          // [3][12][ABW] float2
constexpr int SZ_HC    = 3 * 12 * ABW * 2;        // 9936
constexpr int OFF_ABR  = OFF_HC + SZ_HC;          // [2][3][ABW] float2
constexpr int SZ_ABR   = 2 * 3 * ABW * 2;         // 1656
constexpr int OFF_HAC  = OFF_ABR + SZ_ABR;        // [3][12][CT] float2
constexpr int SZ_HAC   = 3 * 12 * CT * 2;         // 9216
constexpr int OFF_RED  = OFF_HAC + SZ_HAC;
constexpr int SMEM_FLOATS = OFF_RED + NWARP;      // 26309
constexpr int SMEM_BYTES  = SMEM_FLOATS * 4;      // ~105.2 KB -> 2 blocks/SM

__global__ void __launch_bounds__(NTH) fused_loss(
    const float* __restrict__ gen, const float* __restrict__ ir,
    const float* __restrict__ vi, float* __restrict__ out)
{
    extern __shared__ float smf[];
    const int t    = threadIdx.x;
    const int c0   = blockIdx.x * CT;
    const int y0   = blockIdx.y * BANDQ;
    const int band = min(BANDQ, HT - y0);          // 171,171,170
    const size_t pbase = (size_t)blockIdx.z * EPLANE;
    const float* xin0 = ir  + pbase;   // p=0: ir
    const float* xin1 = vi  + pbase;   // p=1: vi
    const float* xin2 = gen + pbase;   // p=2: gen

    float*  rowx = smf + OFF_ROWX;                 // [buf][p][XW]
    float*  xc   = smf + OFF_XC;                   // [p][slot12][CT]
    float2* hc   = (float2*)(smf + OFF_HC);        // [p][slot12][ABW]
    float2* abr  = (float2*)(smf + OFF_ABR);       // [buf][p][ABW]
    float2* hac  = (float2*)(smf + OFF_HAC);       // [p][slot12][CT]
    float*  red  = smf + OFF_RED;

    float S1[3] = {0,0,0}, S2[3] = {0,0,0};        // stage-1 vertical running sums
    float T1[3] = {0,0,0}, T2[3] = {0,0,0};        // stage-2 vertical running sums
    float lacc = 0.f;
    int xs = 0, hs = 0, has = 0, buf = 0;

    for (int yi = y0 - 10; yi < y0 + band + 10; ++yi) {
        float*  rx = rowx + buf * (3 * XW);
        float2* ab = abr  + buf * (3 * ABW);

        // ---- phase 1: ingest x row yi (zero outside image) ----------------
        if (t < XW) {
            const int col = c0 - 10 + t;
            const bool in = ((unsigned)yi < (unsigned)HT) && ((unsigned)col < (unsigned)WD);
            const size_t gidx = (size_t)yi * WD + col;
            float v0 = in ? __ldg(xin0 + gidx) : 0.f;
            float v1 = in ? __ldg(xin1 + gidx) : 0.f;
            float v2 = in ? __ldg(xin2 + gidx) : 0.f;
            rx[0 * XW + t] = v0;
            rx[1 * XW + t] = v1;
            rx[2 * XW + t] = v2;
            if (t >= 10 && t < 10 + CT) {
                const int tc = t - 10;
                xc[(0 * 12 + xs) * CT + tc] = v0;
                xc[(1 * 12 + xs) * CT + tc] = v1;
                xc[(2 * 12 + xs) * CT + tc] = v2;
            }
        }
        __syncthreads();

        // ---- phase 2: horizontal 11-tap of x,x^2; vertical running sums; a,b row
        const int hso = (hs + 1 == 12) ? 0 : hs + 1;   // slot of h[yi-11]
        if (t < ABW) {
            const bool doSub = (yi >= y0 + 1);
            const bool doAB  = (yi >= y0);
            const int  ya    = yi - 5;
            const int  colab = c0 - 5 + t;
            const bool abIn  = ((unsigned)ya < (unsigned)HT) && ((unsigned)colab < (unsigned)WD);
#pragma unroll
            for (int p = 0; p < 3; ++p) {
                const float* r = rx + p * XW;
                float s1 = 0.f, s2 = 0.f;
#pragma unroll
                for (int k = 0; k < 11; ++k) {
                    float u = r[t + k];
                    s1 += u;
                    s2 = fmaf(u, u, s2);
                }
                S1[p] += s1; S2[p] += s2;
                if (doSub) {
                    float2 o = hc[(p * 12 + hso) * ABW + t];
                    S1[p] -= o.x; S2[p] -= o.y;
                }
                hc[(p * 12 + hs) * ABW + t] = make_float2(s1, s2);
                if (doAB) {
                    float2 v = make_float2(0.f, 0.f);
                    if (abIn) {
                        float mean = S1[p] * INV_KK;
                        float corr = S2[p] * INV_KK;
                        float var  = corr - mean * mean;
                        float aa   = var / (var + EPSV);
                        v = make_float2(aa, mean - aa * mean);
                    }
                    ab[p * ABW + t] = v;
                }
            }
        }
        __syncthreads();

        // ---- phase 3: horizontal 11-tap of a,b; vertical running sums; emit
        if (yi >= y0 && t < CT) {
            const int ya   = yi - 5;
            const int haso = (has + 1 == 12) ? 0 : has + 1;
            const bool doSub = (ya >= y0 + 6);
            float ma[3], mb[3];
#pragma unroll
            for (int p = 0; p < 3; ++p) {
                const float2* a = ab + p * ABW;
                float h1 = 0.f, h2 = 0.f;
#pragma unroll
                for (int k = 0; k < 11; ++k) {
                    float2 u = a[t + k];
                    h1 += u.x; h2 += u.y;
                }
                T1[p] += h1; T2[p] += h2;
                if (doSub) {
                    float2 o = hac[(p * 12 + haso) * CT + t];
                    T1[p] -= o.x; T2[p] -= o.y;
                }
                hac[(p * 12 + has) * CT + t] = make_float2(h1, h2);
                ma[p] = T1[p] * INV_KK;
                mb[p] = T2[p] * INV_KK;
            }
            if (yi >= y0 + 10) {
                // x row yi-10 was written 10 iterations ago -> slot (xs+2)%12
                const int xr = (xs + 2 >= 12) ? xs + 2 - 12 : xs + 2;
                float f[3];
#pragma unroll
                for (int p = 0; p < 3; ++p) {
                    float xv = xc[(p * 12 + xr) * CT + t];
                    f[p] = xv - fmaf(ma[p], xv, mb[p]);
                }
                lacc += fabsf(f[2] - fmaxf(fabsf(f[0]), fabsf(f[1])));
            }
        }

        // ---- advance circular slots --------------------------------------
        xs = (xs + 1 == 12) ? 0 : xs + 1;
        hs = (hs + 1 == 12) ? 0 : hs + 1;
        if (yi >= y0) has = (has + 1 == 12) ? 0 : has + 1;
        buf ^= 1;
    }

    // ---- block reduction + atomic ----------------------------------------
#pragma unroll
    for (int o = 16; o; o >>= 1) lacc += __shfl_down_sync(0xffffffffu, lacc, o);
    if ((t & 31) == 0) red[t >> 5] = lacc;
    __syncthreads();
    if (t == 0) {
        float v = red[0] + red[1] + red[2] + red[3] + red[4];
        atomicAdd(out, v * SCALE);
    }
}

__global__ void zero_out(float* out) { out[0] = 0.f; }

// ---------------------------------------------------------------------------
extern "C" void kernel_launch(void* const* d_in, const int* in_sizes, int n_in,
                              void* d_out, int out_size) {
    const float* gen = (const float*)d_in[0];
    const float* ir  = (const float*)d_in[1];
    const float* vi  = (const float*)d_in[2];
    float* out = (float*)d_out;

    cudaFuncSetAttribute(fused_loss, cudaFuncAttributeMaxDynamicSharedMemorySize,
                         SMEM_BYTES);

    zero_out<<<1, 1>>>(out);
    dim3 grid(WD / CT, 3, NPL);   // (4, 3, 24) = 288 blocks, bands 171/171/170
    fused_loss<<<grid, NTH, SMEM_BYTES>>>(gen, ir, vi, out);
}